// round 11
// baseline (speedup 1.0000x reference)
#include <cuda_runtime.h>
#include <cuda_fp16.h>
#include <cstdint>

#define MAX_N 100000
#define MAX_E 1600000
#define DD 128
#define MAX_G 512

// ---------------- scratch ----------------
__device__ int   g_deg[MAX_N];
__device__ int   g_fill[MAX_N];
__device__ int   g_rs[MAX_N + 1];
__device__ int   g_bsums[256];
__device__ float g_dis[MAX_N];
__device__ int2  g_cm[MAX_E];
__device__ __half g_hA[(size_t)MAX_N * DD];     // ping
__device__ __half g_hB[(size_t)MAX_N * DD];     // pong
__device__ __half g_wt[3][DD * DD];             // W^T fp16
__device__ float g_gsum[MAX_G];
__device__ float g_gcnt[MAX_G];

// ---------------- helpers ----------------
__device__ __forceinline__ uint32_t smem_u32(const void* p) {
    uint32_t a;
    asm("{ .reg .u64 t; cvta.to.shared.u64 t, %1; cvt.u32.u64 %0, t; }" : "=r"(a) : "l"(p));
    return a;
}
#define CP_ASYNC16(dst_u32, src_ptr) \
    asm volatile("cp.async.cg.shared.global [%0], [%1], 16;" :: "r"(dst_u32), "l"(src_ptr))
#define CP_COMMIT() asm volatile("cp.async.commit_group;")
#define CP_WAIT0()  asm volatile("cp.async.wait_group 0;")

// ---------------- setup kernels ----------------
__global__ void k_zero(int* __restrict__ deg, int* __restrict__ fill,
                       float* __restrict__ gsum, float* __restrict__ gcnt,
                       int N, int G) {
    int i = blockIdx.x * blockDim.x + threadIdx.x;
    if (i < N) { deg[i] = 0; fill[i] = 0; }
    if (i < G) { gsum[i] = 0.f; gcnt[i] = 0.f; }
}

__global__ void k_count(const int* __restrict__ ei, int E, int* __restrict__ deg) {
    int e4 = blockIdx.x * blockDim.x + threadIdx.x;
    int base = e4 * 4;
    if (base + 3 < E) {
        int4 d = *(const int4*)(ei + E + base);
        atomicAdd(&deg[d.x], 1);
        atomicAdd(&deg[d.y], 1);
        atomicAdd(&deg[d.z], 1);
        atomicAdd(&deg[d.w], 1);
    } else {
        for (int e = base; e < E; e++) atomicAdd(&deg[ei[E + e]], 1);
    }
}

__global__ __launch_bounds__(256) void k_scan1(const int* __restrict__ in,
                                               int* __restrict__ out,
                                               int* __restrict__ bsums,
                                               float* __restrict__ dis, int N) {
    __shared__ int sm[256];
    int t = threadIdx.x;
    int base = blockIdx.x * 1024 + t * 4;
    int v0 = (base + 0 < N) ? in[base + 0] : 0;
    int v1 = (base + 1 < N) ? in[base + 1] : 0;
    int v2 = (base + 2 < N) ? in[base + 2] : 0;
    int v3 = (base + 3 < N) ? in[base + 3] : 0;
    if (base + 0 < N) dis[base + 0] = rsqrtf((float)v0 + 1.0f);
    if (base + 1 < N) dis[base + 1] = rsqrtf((float)v1 + 1.0f);
    if (base + 2 < N) dis[base + 2] = rsqrtf((float)v2 + 1.0f);
    if (base + 3 < N) dis[base + 3] = rsqrtf((float)v3 + 1.0f);
    int ts = v0 + v1 + v2 + v3;
    sm[t] = ts;
    __syncthreads();
    for (int off = 1; off < 256; off <<= 1) {
        int x = (t >= off) ? sm[t - off] : 0;
        __syncthreads();
        sm[t] += x;
        __syncthreads();
    }
    int run = sm[t] - ts;
    if (base + 0 < N) out[base + 0] = run; run += v0;
    if (base + 1 < N) out[base + 1] = run; run += v1;
    if (base + 2 < N) out[base + 2] = run; run += v2;
    if (base + 3 < N) out[base + 3] = run;
    if (t == 255) bsums[blockIdx.x] = sm[255];
}

__global__ __launch_bounds__(128) void k_scan2(int* __restrict__ bsums, int nb) {
    __shared__ int sm[128];
    int t = threadIdx.x;
    int v = (t < nb) ? bsums[t] : 0;
    sm[t] = v;
    __syncthreads();
    for (int off = 1; off < 128; off <<= 1) {
        int x = (t >= off) ? sm[t - off] : 0;
        __syncthreads();
        sm[t] += x;
        __syncthreads();
    }
    if (t < nb) bsums[t] = sm[t] - v;
}

__global__ void k_fill(const int* __restrict__ ei, int E,
                       const int* __restrict__ rs, const int* __restrict__ bs,
                       int* __restrict__ fill,
                       const float* __restrict__ dis,
                       int2* __restrict__ cm) {
    int e2 = blockIdx.x * blockDim.x + threadIdx.x;
    int base = e2 * 2;
    if (base >= E) return;
    if (base + 1 < E) {
        int2 s = *(const int2*)(ei + base);
        int2 d = *(const int2*)(ei + E + base);
        int slot0 = rs[d.x] + bs[d.x >> 10] + atomicAdd(&fill[d.x], 1);
        int slot1 = rs[d.y] + bs[d.y >> 10] + atomicAdd(&fill[d.y], 1);
        cm[slot0] = make_int2(s.x, __float_as_int(dis[s.x] * dis[d.x]));
        cm[slot1] = make_int2(s.y, __float_as_int(dis[s.y] * dis[d.y]));
    } else {
        int src = ei[base], dst = ei[E + base];
        int slot = rs[dst] + bs[dst >> 10] + atomicAdd(&fill[dst], 1);
        cm[slot] = make_int2(src, __float_as_int(dis[src] * dis[dst]));
    }
}

// x -> fp16 table (layer-0 input)
__global__ void k_xconv(const float* __restrict__ x, __half* __restrict__ h, int total4) {
    int i = blockIdx.x * blockDim.x + threadIdx.x;
    if (i >= total4) return;
    float4 v = ((const float4*)x)[i];
    ((__half2*)h)[i * 2 + 0] = __floats2half2_rn(v.x, v.y);
    ((__half2*)h)[i * 2 + 1] = __floats2half2_rn(v.z, v.w);
}

__global__ void k_wprep3(const float* __restrict__ W1, const float* __restrict__ W2,
                         const float* __restrict__ W3, __half* __restrict__ wt) {
    int i = blockIdx.x * blockDim.x + threadIdx.x;
    if (i >= 3 * DD * DD) return;
    int l = i / (DD * DD);
    int j = i % (DD * DD);
    int n = j >> 7, k = j & 127;
    const float* W = (l == 0) ? W1 : (l == 1) ? W2 : W3;
    wt[i] = __float2half_rn(W[k * DD + n]);
}

// ---------------- aggregate core (unrolled x4) ----------------
__device__ __forceinline__ void agg_core(const uint2* __restrict__ HT2,
                                         const int2* __restrict__ cm,
                                         int s0, int s1, int lane,
                                         float& ax, float& ay, float& az, float& aw) {
    int i = s0;
    for (; i + 3 < s1; i += 4) {
        int2 m0 = __ldg(&cm[i]);
        int2 m1 = __ldg(&cm[i + 1]);
        int2 m2 = __ldg(&cm[i + 2]);
        int2 m3 = __ldg(&cm[i + 3]);
        uint2 v0 = __ldg(&HT2[((size_t)m0.x << 5) + lane]);
        uint2 v1 = __ldg(&HT2[((size_t)m1.x << 5) + lane]);
        uint2 v2 = __ldg(&HT2[((size_t)m2.x << 5) + lane]);
        uint2 v3 = __ldg(&HT2[((size_t)m3.x << 5) + lane]);
        float e0 = __int_as_float(m0.y), e1 = __int_as_float(m1.y);
        float e2 = __int_as_float(m2.y), e3 = __int_as_float(m3.y);
        float2 a0 = __half22float2(*(__half2*)&v0.x), b0 = __half22float2(*(__half2*)&v0.y);
        float2 a1 = __half22float2(*(__half2*)&v1.x), b1 = __half22float2(*(__half2*)&v1.y);
        float2 a2 = __half22float2(*(__half2*)&v2.x), b2 = __half22float2(*(__half2*)&v2.y);
        float2 a3 = __half22float2(*(__half2*)&v3.x), b3 = __half22float2(*(__half2*)&v3.y);
        ax += e0 * a0.x + e1 * a1.x + e2 * a2.x + e3 * a3.x;
        ay += e0 * a0.y + e1 * a1.y + e2 * a2.y + e3 * a3.y;
        az += e0 * b0.x + e1 * b1.x + e2 * b2.x + e3 * b3.x;
        aw += e0 * b0.y + e1 * b1.y + e2 * b2.y + e3 * b3.y;
    }
    for (; i < s1; i++) {
        int2 m0 = __ldg(&cm[i]);
        uint2 v0 = __ldg(&HT2[((size_t)m0.x << 5) + lane]);
        float e0 = __int_as_float(m0.y);
        float2 a0 = __half22float2(*(__half2*)&v0.x);
        float2 b0 = __half22float2(*(__half2*)&v0.y);
        ax += e0 * a0.x; ay += e0 * a0.y; az += e0 * b0.x; aw += e0 * b0.y;
    }
}

// ============== FUSED layer: Hout = relu( agg(H) @ W^T + b ) ==============
// agg(h·W) = agg(h)·W (aggregation is linear) — gather directly into A tile.
__device__ __forceinline__ uint32_t sw_off(int row, int byte_in_row) {
    int chunk = byte_in_row >> 4;
    int within = byte_in_row & 15;
    return (uint32_t)(row * 256 + (((chunk ^ (row & 7)) << 4) | within));
}

__device__ __forceinline__ void mma16816(float& c0, float& c1, float& c2, float& c3,
                                         uint32_t a0, uint32_t a1, uint32_t a2, uint32_t a3,
                                         uint32_t b0, uint32_t b1) {
    asm volatile(
        "mma.sync.aligned.m16n8k16.row.col.f32.f16.f16.f32 "
        "{%0,%1,%2,%3}, {%4,%5,%6,%7}, {%8,%9}, {%0,%1,%2,%3};"
        : "+f"(c0), "+f"(c1), "+f"(c2), "+f"(c3)
        : "r"(a0), "r"(a1), "r"(a2), "r"(a3), "r"(b0), "r"(b1));
}

__global__ __launch_bounds__(256, 2) void k_fused(
    const __half* __restrict__ H, const __half* __restrict__ Wt,
    __half* __restrict__ Hout,
    const int* __restrict__ rs, const int* __restrict__ bs,
    const int* __restrict__ deg, const int2* __restrict__ cm,
    const float* __restrict__ dis, const float* __restrict__ bias, int N) {
    extern __shared__ char smem[];
    int tid = threadIdx.x;
    int wid = tid >> 5;
    int lane = tid & 31;
    int g = lane >> 2;
    int t = lane & 3;
    int n0 = blockIdx.x * 128;
    int warp_m = (wid & 3) * 32;
    int warp_n = (wid >> 2) * 64;
    uint32_t smem_b = smem_u32(smem);

    // B tile (W^T) via cp.async — overlaps the gather below
    for (int i = tid; i < 2048; i += 256) {
        int row = i >> 4;
        int c   = i & 15;
        uint32_t dst = smem_b + 32768 + (uint32_t)(row * 256 + ((c ^ (row & 7)) << 4));
        CP_ASYNC16(dst, (const char*)(Wt + ((size_t)row << 7)) + c * 16);
    }
    CP_COMMIT();

    // gather + aggregate 16 rows per warp, write fp16 into swizzled A tile
    const uint2* HT2 = (const uint2*)H;
    {
        uint32_t chunk  = (uint32_t)(lane >> 1);
        uint32_t within = (uint32_t)((lane & 1) * 8);
#pragma unroll 1
        for (int j = 0; j < 16; j++) {
            int row = wid * 16 + j;
            int w = n0 + row;
            float ax = 0.f, ay = 0.f, az = 0.f, aw = 0.f;
            if (w < N) {
                int s0 = rs[w] + bs[w >> 10];
                int s1 = s0 + deg[w];
                agg_core(HT2, cm, s0, s1, lane, ax, ay, az, aw);
                float dn = dis[w];
                float sn = dn * dn;
                uint2 sv = __ldg(&HT2[((size_t)w << 5) + lane]);
                float2 s0f = __half22float2(*(__half2*)&sv.x);
                float2 s1f = __half22float2(*(__half2*)&sv.y);
                ax += sn * s0f.x; ay += sn * s0f.y;
                az += sn * s1f.x; aw += sn * s1f.y;
            }
            __half2 p0 = __floats2half2_rn(ax, ay);
            __half2 p1 = __floats2half2_rn(az, aw);
            uint32_t off = (uint32_t)(row * 256 + (((chunk ^ (uint32_t)(row & 7)) << 4) | within));
            *(uint2*)(smem + off) = make_uint2(*(uint32_t*)&p0, *(uint32_t*)&p1);
        }
    }
    CP_WAIT0();
    __syncthreads();

    // MMA: A (agg tile) @ B (W^T), fp32 accum
    float acc[2][8][4];
#pragma unroll
    for (int mt = 0; mt < 2; mt++)
#pragma unroll
        for (int nt = 0; nt < 8; nt++)
#pragma unroll
            for (int q = 0; q < 4; q++) acc[mt][nt][q] = 0.f;

    const char* As = smem;
    const char* Bs = smem + 32768;
#pragma unroll
    for (int ks = 0; ks < 8; ks++) {
        int byte0 = ks * 32 + t * 4;
        uint32_t a[2][4];
#pragma unroll
        for (int mt = 0; mt < 2; mt++) {
            int r = warp_m + mt * 16 + g;
            a[mt][0] = *(const uint32_t*)(As + sw_off(r,     byte0));
            a[mt][1] = *(const uint32_t*)(As + sw_off(r + 8, byte0));
            a[mt][2] = *(const uint32_t*)(As + sw_off(r,     byte0 + 16));
            a[mt][3] = *(const uint32_t*)(As + sw_off(r + 8, byte0 + 16));
        }
        uint32_t bfr[8][2];
#pragma unroll
        for (int nt = 0; nt < 8; nt++) {
            int n = warp_n + nt * 8 + g;
            bfr[nt][0] = *(const uint32_t*)(Bs + sw_off(n, byte0));
            bfr[nt][1] = *(const uint32_t*)(Bs + sw_off(n, byte0 + 16));
        }
#pragma unroll
        for (int mt = 0; mt < 2; mt++)
#pragma unroll
            for (int nt = 0; nt < 8; nt++)
                mma16816(acc[mt][nt][0], acc[mt][nt][1], acc[mt][nt][2], acc[mt][nt][3],
                         a[mt][0], a[mt][1], a[mt][2], a[mt][3],
                         bfr[nt][0], bfr[nt][1]);
    }

    // epilogue: + bias, relu, fp16 write
#pragma unroll
    for (int mt = 0; mt < 2; mt++) {
        int r0 = n0 + warp_m + mt * 16 + g;
#pragma unroll
        for (int nt = 0; nt < 8; nt++) {
            int col = warp_n + nt * 8 + t * 2;
            float2 bb = *(const float2*)(bias + col);
            if (r0 < N)
                *(__half2*)(Hout + ((size_t)r0 << 7) + col) =
                    __floats2half2_rn(fmaxf(acc[mt][nt][0] + bb.x, 0.f),
                                      fmaxf(acc[mt][nt][1] + bb.y, 0.f));
            if (r0 + 8 < N)
                *(__half2*)(Hout + ((size_t)(r0 + 8) << 7) + col) =
                    __floats2half2_rn(fmaxf(acc[mt][nt][2] + bb.x, 0.f),
                                      fmaxf(acc[mt][nt][3] + bb.y, 0.f));
        }
    }
}

// ---------------- pool: per-node dot with Wfc + mean per graph ----------------
__global__ __launch_bounds__(256) void k_pool(const __half* __restrict__ H,
                                              const int* __restrict__ batch,
                                              const float* __restrict__ Wfc,
                                              float* __restrict__ gsum,
                                              float* __restrict__ gcnt, int N) {
    int w    = (blockIdx.x * blockDim.x + threadIdx.x) >> 5;
    int lane = threadIdx.x & 31;
    if (w >= N) return;
    uint2 v = __ldg(&((const uint2*)H)[((size_t)w << 5) + lane]);
    float2 f0 = __half22float2(*(__half2*)&v.x);
    float2 f1 = __half22float2(*(__half2*)&v.y);
    float4 f = *(const float4*)(Wfc + (lane << 2));
    float s = f0.x * f.x + f0.y * f.y + f1.x * f.z + f1.y * f.w;
#pragma unroll
    for (int off = 16; off; off >>= 1) s += __shfl_down_sync(0xffffffffu, s, off);
    if (lane == 0) {
        int gg = batch[w];
        atomicAdd(&gsum[gg], s);
        atomicAdd(&gcnt[gg], 1.0f);
    }
}

__global__ void k_final(const float* __restrict__ gsum, const float* __restrict__ gcnt,
                        const float* __restrict__ bfc, float* __restrict__ out, int G) {
    int g = blockIdx.x * blockDim.x + threadIdx.x;
    if (g < G) out[g] = gsum[g] / fmaxf(gcnt[g], 1.0f) + bfc[0];
}

// ---------------- host ----------------
extern "C" void kernel_launch(void* const* d_in, const int* in_sizes, int n_in,
                              void* d_out, int out_size) {
    const float* x    = (const float*)d_in[0];
    const int*   ei   = (const int*)d_in[1];
    const int*   bat  = (const int*)d_in[2];
    const float* W1   = (const float*)d_in[3];
    const float* b1   = (const float*)d_in[4];
    const float* W2   = (const float*)d_in[5];
    const float* b2   = (const float*)d_in[6];
    const float* W3   = (const float*)d_in[7];
    const float* b3   = (const float*)d_in[8];
    const float* Wfc  = (const float*)d_in[9];
    const float* bfc  = (const float*)d_in[10];
    float* out = (float*)d_out;

    int N = in_sizes[2];
    int E = in_sizes[1] / 2;
    int G = out_size;

    void *p;
    cudaGetSymbolAddress(&p, g_deg);    int* deg = (int*)p;
    cudaGetSymbolAddress(&p, g_fill);   int* fill = (int*)p;
    cudaGetSymbolAddress(&p, g_rs);     int* rs = (int*)p;
    cudaGetSymbolAddress(&p, g_bsums);  int* bsum = (int*)p;
    cudaGetSymbolAddress(&p, g_dis);    float* dis = (float*)p;
    cudaGetSymbolAddress(&p, g_cm);     int2* cm = (int2*)p;
    cudaGetSymbolAddress(&p, g_hA);     __half* hA = (__half*)p;
    cudaGetSymbolAddress(&p, g_hB);     __half* hB = (__half*)p;
    cudaGetSymbolAddress(&p, g_wt);     __half* wt = (__half*)p;
    cudaGetSymbolAddress(&p, g_gsum);   float* gsum = (float*)p;
    cudaGetSymbolAddress(&p, g_gcnt);   float* gcnt = (float*)p;

    cudaFuncSetAttribute(k_fused, cudaFuncAttributeMaxDynamicSharedMemorySize, 65536);

    int tiles = (N + 127) / 128;
    int mx = (N > G) ? N : G;
    int nb = (N + 1023) / 1024;
    int total4 = N * DD / 4;

    k_wprep3<<<(3 * DD * DD + 255) / 256, 256>>>(W1, W2, W3, wt);
    k_xconv<<<(total4 + 255) / 256, 256>>>(x, hA, total4);
    k_zero<<<(mx + 255) / 256, 256>>>(deg, fill, gsum, gcnt, N, G);
    k_count<<<((E + 3) / 4 + 255) / 256, 256>>>(ei, E, deg);
    k_scan1<<<nb, 256>>>(deg, rs, bsum, dis, N);
    k_scan2<<<1, 128>>>(bsum, nb);
    k_fill<<<((E + 1) / 2 + 255) / 256, 256>>>(ei, E, rs, bsum, fill, dis, cm);

    // 3 fused layers: Hout = relu(agg(H) @ W^T + b); ping-pong hA/hB
    k_fused<<<tiles, 256, 65536>>>(hA, wt,              hB, rs, bsum, deg, cm, dis, b1, N);
    k_fused<<<tiles, 256, 65536>>>(hB, wt + DD * DD,    hA, rs, bsum, deg, cm, dis, b2, N);
    k_fused<<<tiles, 256, 65536>>>(hA, wt + 2 * DD * DD, hB, rs, bsum, deg, cm, dis, b3, N);

    k_pool<<<(N + 7) / 8, 256>>>(hB, bat, Wfc, gsum, gcnt, N);
    k_final<<<(G + 255) / 256, 256>>>(gsum, gcnt, bfc, out, G);
}

// round 12
// speedup vs baseline: 1.8836x; 1.8836x over previous
#include <cuda_runtime.h>
#include <cuda_fp16.h>
#include <cstdint>

#define MAX_N 100000
#define MAX_E 1600000
#define DD 128
#define MAX_G 512

// ---------------- scratch ----------------
__device__ int   g_deg[MAX_N];
__device__ int   g_fill[MAX_N];
__device__ int   g_rs[MAX_N + 1];
__device__ int   g_bsums[256];
__device__ float g_dis[MAX_N];
__device__ int   g_cs[MAX_E];                   // CSR: src only (dis folded into table)
__device__ __half g_bufH[(size_t)MAX_N * DD];   // GEMM output: dis[n]*(hW)[n]
__device__ __half g_hi[(size_t)MAX_N * DD];     // GEMM input (fp16 h table)
__device__ __half g_wt[3][DD * DD];             // W^T fp16
__device__ float g_gsum[MAX_G];
__device__ float g_gcnt[MAX_G];

// ---------------- helpers ----------------
__device__ __forceinline__ uint32_t smem_u32(const void* p) {
    uint32_t a;
    asm("{ .reg .u64 t; cvta.to.shared.u64 t, %1; cvt.u32.u64 %0, t; }" : "=r"(a) : "l"(p));
    return a;
}
#define CP_ASYNC16(dst_u32, src_ptr) \
    asm volatile("cp.async.cg.shared.global [%0], [%1], 16;" :: "r"(dst_u32), "l"(src_ptr))
#define CP_COMMIT() asm volatile("cp.async.commit_group;")
#define CP_WAIT0()  asm volatile("cp.async.wait_group 0;")

// ---------------- setup kernels ----------------
__global__ void k_zero(int* __restrict__ deg, int* __restrict__ fill,
                       float* __restrict__ gsum, float* __restrict__ gcnt,
                       int N, int G) {
    int i = blockIdx.x * blockDim.x + threadIdx.x;
    if (i < N) { deg[i] = 0; fill[i] = 0; }
    if (i < G) { gsum[i] = 0.f; gcnt[i] = 0.f; }
}

__global__ void k_count(const int* __restrict__ ei, int E, int* __restrict__ deg) {
    int e4 = blockIdx.x * blockDim.x + threadIdx.x;
    int base = e4 * 4;
    if (base + 3 < E) {
        int4 d = *(const int4*)(ei + E + base);
        atomicAdd(&deg[d.x], 1);
        atomicAdd(&deg[d.y], 1);
        atomicAdd(&deg[d.z], 1);
        atomicAdd(&deg[d.w], 1);
    } else {
        for (int e = base; e < E; e++) atomicAdd(&deg[ei[E + e]], 1);
    }
}

__global__ __launch_bounds__(256) void k_scan1(const int* __restrict__ in,
                                               int* __restrict__ out,
                                               int* __restrict__ bsums,
                                               float* __restrict__ dis, int N) {
    __shared__ int sm[256];
    int t = threadIdx.x;
    int base = blockIdx.x * 1024 + t * 4;
    int v0 = (base + 0 < N) ? in[base + 0] : 0;
    int v1 = (base + 1 < N) ? in[base + 1] : 0;
    int v2 = (base + 2 < N) ? in[base + 2] : 0;
    int v3 = (base + 3 < N) ? in[base + 3] : 0;
    if (base + 0 < N) dis[base + 0] = rsqrtf((float)v0 + 1.0f);
    if (base + 1 < N) dis[base + 1] = rsqrtf((float)v1 + 1.0f);
    if (base + 2 < N) dis[base + 2] = rsqrtf((float)v2 + 1.0f);
    if (base + 3 < N) dis[base + 3] = rsqrtf((float)v3 + 1.0f);
    int ts = v0 + v1 + v2 + v3;
    sm[t] = ts;
    __syncthreads();
    for (int off = 1; off < 256; off <<= 1) {
        int x = (t >= off) ? sm[t - off] : 0;
        __syncthreads();
        sm[t] += x;
        __syncthreads();
    }
    int run = sm[t] - ts;
    if (base + 0 < N) out[base + 0] = run; run += v0;
    if (base + 1 < N) out[base + 1] = run; run += v1;
    if (base + 2 < N) out[base + 2] = run; run += v2;
    if (base + 3 < N) out[base + 3] = run;
    if (t == 255) bsums[blockIdx.x] = sm[255];
}

__global__ __launch_bounds__(128) void k_scan2(int* __restrict__ bsums, int nb) {
    __shared__ int sm[128];
    int t = threadIdx.x;
    int v = (t < nb) ? bsums[t] : 0;
    sm[t] = v;
    __syncthreads();
    for (int off = 1; off < 128; off <<= 1) {
        int x = (t >= off) ? sm[t - off] : 0;
        __syncthreads();
        sm[t] += x;
        __syncthreads();
    }
    if (t < nb) bsums[t] = sm[t] - v;
}

// fill src-only CSR
__global__ void k_fill(const int* __restrict__ ei, int E,
                       const int* __restrict__ rs, const int* __restrict__ bs,
                       int* __restrict__ fill, int* __restrict__ cs) {
    int e4 = blockIdx.x * blockDim.x + threadIdx.x;
    int base = e4 * 4;
    if (base >= E) return;
    if (base + 3 < E) {
        int4 s = *(const int4*)(ei + base);
        int4 d = *(const int4*)(ei + E + base);
        cs[rs[d.x] + bs[d.x >> 10] + atomicAdd(&fill[d.x], 1)] = s.x;
        cs[rs[d.y] + bs[d.y >> 10] + atomicAdd(&fill[d.y], 1)] = s.y;
        cs[rs[d.z] + bs[d.z >> 10] + atomicAdd(&fill[d.z], 1)] = s.z;
        cs[rs[d.w] + bs[d.w >> 10] + atomicAdd(&fill[d.w], 1)] = s.w;
    } else {
        for (int e = base; e < E; e++) {
            int src = ei[e], dst = ei[E + e];
            cs[rs[dst] + bs[dst >> 10] + atomicAdd(&fill[dst], 1)] = src;
        }
    }
}

// x -> fp16 table
__global__ void k_xconv(const float* __restrict__ x, __half* __restrict__ h, int total4) {
    int i = blockIdx.x * blockDim.x + threadIdx.x;
    if (i >= total4) return;
    float4 v = ((const float4*)x)[i];
    ((__half2*)h)[i * 2 + 0] = __floats2half2_rn(v.x, v.y);
    ((__half2*)h)[i * 2 + 1] = __floats2half2_rn(v.z, v.w);
}

__global__ void k_wprep3(const float* __restrict__ W1, const float* __restrict__ W2,
                         const float* __restrict__ W3, __half* __restrict__ wt) {
    int i = blockIdx.x * blockDim.x + threadIdx.x;
    if (i >= 3 * DD * DD) return;
    int l = i / (DD * DD);
    int j = i % (DD * DD);
    int n = j >> 7, k = j & 127;
    const float* W = (l == 0) ? W1 : (l == 1) ? W2 : W3;
    wt[i] = __float2half_rn(W[k * DD + n]);
}

// ============== GEMM: O[n] = dis[n] * (H[n] @ W^T), fp16 in/out, fp32 accum ==============
__device__ __forceinline__ uint32_t sw_off(int row, int byte_in_row) {
    int chunk = byte_in_row >> 4;
    int within = byte_in_row & 15;
    return (uint32_t)(row * 256 + (((chunk ^ (row & 7)) << 4) | within));
}

__device__ __forceinline__ void mma16816(float& c0, float& c1, float& c2, float& c3,
                                         uint32_t a0, uint32_t a1, uint32_t a2, uint32_t a3,
                                         uint32_t b0, uint32_t b1) {
    asm volatile(
        "mma.sync.aligned.m16n8k16.row.col.f32.f16.f16.f32 "
        "{%0,%1,%2,%3}, {%4,%5,%6,%7}, {%8,%9}, {%0,%1,%2,%3};"
        : "+f"(c0), "+f"(c1), "+f"(c2), "+f"(c3)
        : "r"(a0), "r"(a1), "r"(a2), "r"(a3), "r"(b0), "r"(b1));
}

__global__ __launch_bounds__(256, 2) void k_gemm_mma(
    const __half* __restrict__ A, const __half* __restrict__ B,
    __half* __restrict__ O, const float* __restrict__ dis, int N) {
    extern __shared__ char smem[];
    int tid = threadIdx.x;
    int wid = tid >> 5;
    int lane = tid & 31;
    int g = lane >> 2;
    int t = lane & 3;
    int n0 = blockIdx.x * 128;
    int warp_m = (wid & 3) * 32;
    int warp_n = (wid >> 2) * 64;
    uint32_t smem_b = smem_u32(smem);

    // B tile (W^T)
    for (int i = tid; i < 2048; i += 256) {
        int row = i >> 4;
        int c   = i & 15;
        uint32_t dst = smem_b + 32768 + (uint32_t)(row * 256 + ((c ^ (row & 7)) << 4));
        CP_ASYNC16(dst, (const char*)(B + ((size_t)row << 7)) + c * 16);
    }
    // A tile
    for (int i = tid; i < 2048; i += 256) {
        int row = i >> 4;
        int c   = i & 15;
        int gr  = min(n0 + row, N - 1);
        uint32_t dst = smem_b + (uint32_t)(row * 256 + ((c ^ (row & 7)) << 4));
        CP_ASYNC16(dst, (const char*)(A + ((size_t)gr << 7)) + c * 16);
    }
    CP_COMMIT();
    CP_WAIT0();
    __syncthreads();

    float acc[2][8][4];
#pragma unroll
    for (int mt = 0; mt < 2; mt++)
#pragma unroll
        for (int nt = 0; nt < 8; nt++)
#pragma unroll
            for (int q = 0; q < 4; q++) acc[mt][nt][q] = 0.f;

    const char* As = smem;
    const char* Bs = smem + 32768;
#pragma unroll
    for (int ks = 0; ks < 8; ks++) {
        int byte0 = ks * 32 + t * 4;
        uint32_t a[2][4];
#pragma unroll
        for (int mt = 0; mt < 2; mt++) {
            int r = warp_m + mt * 16 + g;
            a[mt][0] = *(const uint32_t*)(As + sw_off(r,     byte0));
            a[mt][1] = *(const uint32_t*)(As + sw_off(r + 8, byte0));
            a[mt][2] = *(const uint32_t*)(As + sw_off(r,     byte0 + 16));
            a[mt][3] = *(const uint32_t*)(As + sw_off(r + 8, byte0 + 16));
        }
        uint32_t bfr[8][2];
#pragma unroll
        for (int nt = 0; nt < 8; nt++) {
            int n = warp_n + nt * 8 + g;
            bfr[nt][0] = *(const uint32_t*)(Bs + sw_off(n, byte0));
            bfr[nt][1] = *(const uint32_t*)(Bs + sw_off(n, byte0 + 16));
        }
#pragma unroll
        for (int mt = 0; mt < 2; mt++)
#pragma unroll
            for (int nt = 0; nt < 8; nt++)
                mma16816(acc[mt][nt][0], acc[mt][nt][1], acc[mt][nt][2], acc[mt][nt][3],
                         a[mt][0], a[mt][1], a[mt][2], a[mt][3],
                         bfr[nt][0], bfr[nt][1]);
    }

    // epilogue: scale rows by dis[n], write fp16
#pragma unroll
    for (int mt = 0; mt < 2; mt++) {
        int r0 = n0 + warp_m + mt * 16 + g;
        float d0 = (r0 < N)     ? dis[r0]     : 0.f;
        float d1 = (r0 + 8 < N) ? dis[r0 + 8] : 0.f;
#pragma unroll
        for (int nt = 0; nt < 8; nt++) {
            int col = warp_n + nt * 8 + t * 2;
            if (r0 < N)
                *(__half2*)(O + ((size_t)r0 << 7) + col) =
                    __floats2half2_rn(d0 * acc[mt][nt][0], d0 * acc[mt][nt][1]);
            if (r0 + 8 < N)
                *(__half2*)(O + ((size_t)(r0 + 8) << 7) + col) =
                    __floats2half2_rn(d1 * acc[mt][nt][2], d1 * acc[mt][nt][3]);
        }
    }
}

// ---------------- aggregate core: plain sum over src rows (weights folded) ----------------
__device__ __forceinline__ void agg_core(const uint2* __restrict__ HT2,
                                         const int* __restrict__ cs,
                                         int s0, int s1, int lane,
                                         float& ax, float& ay, float& az, float& aw) {
    int i = s0;
    for (; i + 3 < s1; i += 4) {
        int m0 = __ldg(&cs[i]);
        int m1 = __ldg(&cs[i + 1]);
        int m2 = __ldg(&cs[i + 2]);
        int m3 = __ldg(&cs[i + 3]);
        uint2 v0 = __ldg(&HT2[((size_t)m0 << 5) + lane]);
        uint2 v1 = __ldg(&HT2[((size_t)m1 << 5) + lane]);
        uint2 v2 = __ldg(&HT2[((size_t)m2 << 5) + lane]);
        uint2 v3 = __ldg(&HT2[((size_t)m3 << 5) + lane]);
        float2 a0 = __half22float2(*(__half2*)&v0.x), b0 = __half22float2(*(__half2*)&v0.y);
        float2 a1 = __half22float2(*(__half2*)&v1.x), b1 = __half22float2(*(__half2*)&v1.y);
        float2 a2 = __half22float2(*(__half2*)&v2.x), b2 = __half22float2(*(__half2*)&v2.y);
        float2 a3 = __half22float2(*(__half2*)&v3.x), b3 = __half22float2(*(__half2*)&v3.y);
        ax += a0.x + a1.x + a2.x + a3.x;
        ay += a0.y + a1.y + a2.y + a3.y;
        az += b0.x + b1.x + b2.x + b3.x;
        aw += b0.y + b1.y + b2.y + b3.y;
    }
    for (; i < s1; i++) {
        int m0 = __ldg(&cs[i]);
        uint2 v0 = __ldg(&HT2[((size_t)m0 << 5) + lane]);
        float2 a0 = __half22float2(*(__half2*)&v0.x);
        float2 b0 = __half22float2(*(__half2*)&v0.y);
        ax += a0.x; ay += a0.y; az += b0.x; aw += b0.y;
    }
}

// layers 1,2: h' = relu(dis[w]*(sum + self) + b), write fp16
__global__ __launch_bounds__(256) void k_agg(const __half* __restrict__ HT,
                                             __half* __restrict__ ohi,
                                             const int* __restrict__ rs,
                                             const int* __restrict__ bs,
                                             const int* __restrict__ deg,
                                             const int* __restrict__ cs,
                                             const float* __restrict__ dis,
                                             const float* __restrict__ b, int N) {
    int w    = (blockIdx.x * blockDim.x + threadIdx.x) >> 5;
    int lane = threadIdx.x & 31;
    if (w >= N) return;
    int s0 = rs[w] + bs[w >> 10];
    int s1 = s0 + deg[w];
    const uint2* HT2 = (const uint2*)HT;
    float ax = 0.f, ay = 0.f, az = 0.f, aw = 0.f;
    agg_core(HT2, cs, s0, s1, lane, ax, ay, az, aw);

    uint2 sv = __ldg(&HT2[((size_t)w << 5) + lane]);
    float2 s0f = __half22float2(*(__half2*)&sv.x);
    float2 s1f = __half22float2(*(__half2*)&sv.y);
    float dn = dis[w];
    int col = lane << 2;
    float4 bb = *(const float4*)(b + col);
    ax = fmaxf(dn * (ax + s0f.x) + bb.x, 0.f);
    ay = fmaxf(dn * (ay + s0f.y) + bb.y, 0.f);
    az = fmaxf(dn * (az + s1f.x) + bb.z, 0.f);
    aw = fmaxf(dn * (aw + s1f.y) + bb.w, 0.f);

    size_t idx = (size_t)w * 64 + lane * 2;
    ((__half2*)ohi)[idx + 0] = __floats2half2_rn(ax, ay);
    ((__half2*)ohi)[idx + 1] = __floats2half2_rn(az, aw);
}

// layer 3: fused with Wfc-dot + mean pool
__global__ __launch_bounds__(256) void k_agg_pool(const __half* __restrict__ HT,
                                                  const int* __restrict__ rs,
                                                  const int* __restrict__ bs,
                                                  const int* __restrict__ deg,
                                                  const int* __restrict__ cs,
                                                  const float* __restrict__ dis,
                                                  const float* __restrict__ b,
                                                  const int* __restrict__ batch,
                                                  const float* __restrict__ Wfc,
                                                  float* __restrict__ gsum,
                                                  float* __restrict__ gcnt, int N) {
    int w    = (blockIdx.x * blockDim.x + threadIdx.x) >> 5;
    int lane = threadIdx.x & 31;
    if (w >= N) return;
    int s0 = rs[w] + bs[w >> 10];
    int s1 = s0 + deg[w];
    const uint2* HT2 = (const uint2*)HT;
    float ax = 0.f, ay = 0.f, az = 0.f, aw = 0.f;
    agg_core(HT2, cs, s0, s1, lane, ax, ay, az, aw);

    uint2 sv = __ldg(&HT2[((size_t)w << 5) + lane]);
    float2 s0f = __half22float2(*(__half2*)&sv.x);
    float2 s1f = __half22float2(*(__half2*)&sv.y);
    float dn = dis[w];
    int col = lane << 2;
    float4 bb = *(const float4*)(b + col);
    ax = fmaxf(dn * (ax + s0f.x) + bb.x, 0.f);
    ay = fmaxf(dn * (ay + s0f.y) + bb.y, 0.f);
    az = fmaxf(dn * (az + s1f.x) + bb.z, 0.f);
    aw = fmaxf(dn * (aw + s1f.y) + bb.w, 0.f);

    float4 f = *(const float4*)(Wfc + col);
    float s = ax * f.x + ay * f.y + az * f.z + aw * f.w;
#pragma unroll
    for (int off = 16; off; off >>= 1) s += __shfl_down_sync(0xffffffffu, s, off);
    if (lane == 0) {
        int gg = batch[w];
        atomicAdd(&gsum[gg], s);
        atomicAdd(&gcnt[gg], 1.0f);
    }
}

__global__ void k_final(const float* __restrict__ gsum, const float* __restrict__ gcnt,
                        const float* __restrict__ bfc, float* __restrict__ out, int G) {
    int g = blockIdx.x * blockDim.x + threadIdx.x;
    if (g < G) out[g] = gsum[g] / fmaxf(gcnt[g], 1.0f) + bfc[0];
}

// ---------------- host ----------------
extern "C" void kernel_launch(void* const* d_in, const int* in_sizes, int n_in,
                              void* d_out, int out_size) {
    const float* x    = (const float*)d_in[0];
    const int*   ei   = (const int*)d_in[1];
    const int*   bat  = (const int*)d_in[2];
    const float* W1   = (const float*)d_in[3];
    const float* b1   = (const float*)d_in[4];
    const float* W2   = (const float*)d_in[5];
    const float* b2   = (const float*)d_in[6];
    const float* W3   = (const float*)d_in[7];
    const float* b3   = (const float*)d_in[8];
    const float* Wfc  = (const float*)d_in[9];
    const float* bfc  = (const float*)d_in[10];
    float* out = (float*)d_out;

    int N = in_sizes[2];
    int E = in_sizes[1] / 2;
    int G = out_size;

    void *p;
    cudaGetSymbolAddress(&p, g_deg);    int* deg = (int*)p;
    cudaGetSymbolAddress(&p, g_fill);   int* fill = (int*)p;
    cudaGetSymbolAddress(&p, g_rs);     int* rs = (int*)p;
    cudaGetSymbolAddress(&p, g_bsums);  int* bsum = (int*)p;
    cudaGetSymbolAddress(&p, g_dis);    float* dis = (float*)p;
    cudaGetSymbolAddress(&p, g_cs);     int* cs = (int*)p;
    cudaGetSymbolAddress(&p, g_bufH);   __half* bufH = (__half*)p;
    cudaGetSymbolAddress(&p, g_hi);     __half* hi = (__half*)p;
    cudaGetSymbolAddress(&p, g_wt);     __half* wt = (__half*)p;
    cudaGetSymbolAddress(&p, g_gsum);   float* gsum = (float*)p;
    cudaGetSymbolAddress(&p, g_gcnt);   float* gcnt = (float*)p;

    cudaFuncSetAttribute(k_gemm_mma, cudaFuncAttributeMaxDynamicSharedMemorySize, 65536);

    int tiles = (N + 127) / 128;
    int mx = (N > G) ? N : G;
    int nb = (N + 1023) / 1024;
    int total4 = N * DD / 4;

    k_wprep3<<<(3 * DD * DD + 255) / 256, 256>>>(W1, W2, W3, wt);
    k_xconv<<<(total4 + 255) / 256, 256>>>(x, hi, total4);
    k_zero<<<(mx + 255) / 256, 256>>>(deg, fill, gsum, gcnt, N, G);
    k_count<<<((E + 3) / 4 + 255) / 256, 256>>>(ei, E, deg);
    k_scan1<<<nb, 256>>>(deg, rs, bsum, dis, N);
    k_scan2<<<1, 128>>>(bsum, nb);
    k_fill<<<((E + 3) / 4 + 255) / 256, 256>>>(ei, E, rs, bsum, fill, cs);

    const float* bs3[3] = {b1, b2, b3};
    for (int l = 0; l < 3; l++) {
        k_gemm_mma<<<tiles, 256, 65536>>>(hi, wt + l * DD * DD, bufH, dis, N);
        if (l < 2)
            k_agg<<<(N + 7) / 8, 256>>>(bufH, hi, rs, bsum, deg, cs, dis, bs3[l], N);
        else
            k_agg_pool<<<(N + 7) / 8, 256>>>(bufH, rs, bsum, deg, cs, dis, bs3[l],
                                             bat, Wfc, gsum, gcnt, N);
    }

    k_final<<<(G + 255) / 256, 256>>>(gsum, gcnt, bfc, out, G);
}